// round 1
// baseline (speedup 1.0000x reference)
#include <cuda_runtime.h>
#include <cstddef>

#define BB 16
#define TT 2048
#define CC 1024
#define HH 64
#define MM (BB*TT)   // 32768 rows

// Scratch for projected Q,K,V (allocation-free rule: device globals)
__device__ float g_Q[(size_t)MM*HH];
__device__ float g_K[(size_t)MM*HH];
__device__ float g_V[(size_t)MM*HH];

// ---------------------------------------------------------------------------
// Kernel 1: fused QKV projection.  [MM,1024] @ [1024,64] x3 -> g_Q,g_K,g_V
// Block: 256 threads, computes 64 rows x 192 cols (all three outputs),
// so x is read exactly once from HBM.
// ---------------------------------------------------------------------------
__global__ __launch_bounds__(256) void qkv_kernel(
    const float* __restrict__ x,
    const float* __restrict__ Wq,
    const float* __restrict__ Wk,
    const float* __restrict__ Wv)
{
    __shared__ float As[64][36];    // [m][k]  (pad 4 -> float4-aligned, conflict-free)
    __shared__ float Bs[192][36];   // [n][k]  (transposed weights)

    const int tid = threadIdx.x;
    const int tx = tid & 15, ty = tid >> 4;
    const int m0 = blockIdx.x * 64;

    float acc[4][12];
    #pragma unroll
    for (int i = 0; i < 4; i++)
        #pragma unroll
        for (int j = 0; j < 12; j++) acc[i][j] = 0.f;

    for (int k0 = 0; k0 < CC; k0 += 32) {
        // x tile: 64 x 32 = 512 float4, 2 per thread
        #pragma unroll
        for (int t = 0; t < 2; t++) {
            int f = tid + t * 256;
            int row = f >> 3, c4 = f & 7;
            float4 v = *(const float4*)&x[(size_t)(m0 + row) * CC + k0 + c4 * 4];
            *(float4*)&As[row][c4 * 4] = v;
        }
        // W tiles: 3 x (32 x 64) floats, stored transposed [n][k]
        #pragma unroll
        for (int t = 0; t < 6; t++) {
            const int mat = t >> 1;                 // compile-time under unroll
            const float* W = (mat == 0) ? Wq : (mat == 1) ? Wk : Wv;
            int f = tid + (t & 1) * 256;            // 0..511 float4 within matrix
            int r = f >> 4, c4 = f & 15;
            float4 v = *(const float4*)&W[(size_t)(k0 + r) * HH + c4 * 4];
            int n = mat * 64 + c4 * 4;
            Bs[n + 0][r] = v.x; Bs[n + 1][r] = v.y;
            Bs[n + 2][r] = v.z; Bs[n + 3][r] = v.w;
        }
        __syncthreads();

        #pragma unroll
        for (int kk = 0; kk < 32; kk += 4) {
            float4 a4[4];
            #pragma unroll
            for (int i = 0; i < 4; i++) a4[i] = *(float4*)&As[ty + 16 * i][kk];
            #pragma unroll
            for (int j = 0; j < 12; j++) {
                float4 b4 = *(float4*)&Bs[tx + 16 * j][kk];
                #pragma unroll
                for (int i = 0; i < 4; i++) {
                    acc[i][j] += a4[i].x * b4.x + a4[i].y * b4.y
                               + a4[i].z * b4.z + a4[i].w * b4.w;
                }
            }
        }
        __syncthreads();
    }

    // write-out (coalesced across tx)
    #pragma unroll
    for (int j = 0; j < 12; j++) {
        const int mat = j >> 2;                     // compile-time under unroll
        float* O = (mat == 0) ? g_Q : (mat == 1) ? g_K : g_V;
        int col = tx + 16 * (j & 3);
        #pragma unroll
        for (int i = 0; i < 4; i++) {
            int row = m0 + ty + 16 * i;
            O[(size_t)row * HH + col] = acc[i][j];
        }
    }
}

// ---------------------------------------------------------------------------
// Kernel 2: causal flash attention, fp32.  BM=BN=64, H=64, 256 threads.
// grid = (32, 16): blockIdx.y = batch, it = 31 - blockIdx.x (heavy tiles first).
// ---------------------------------------------------------------------------
__global__ __launch_bounds__(256) void attn_kernel(float* __restrict__ out)
{
    extern __shared__ float sm[];
    float (*Qs)[68] = (float(*)[68])(sm);
    float (*Ks)[68] = (float(*)[68])(sm + 64 * 68);
    float (*Vt)[68] = (float(*)[68])(sm + 2 * 64 * 68);   // [h][kv] transposed
    float (*Ps)[68] = (float(*)[68])(sm + 3 * 64 * 68);

    const int tid = threadIdx.x;
    const int tx = tid & 15, ty = tid >> 4;
    const int b  = blockIdx.y;
    const int it = gridDim.x - 1 - blockIdx.x;   // q tile index, heaviest first

    const size_t base = (size_t)b * TT * HH;
    const float scale = 0.03125f;                // 1024^-0.5

    // load Q tile (pre-scaled)
    #pragma unroll
    for (int t = 0; t < 4; t++) {
        int f = tid + t * 256;
        int r = f >> 4, h4 = f & 15;
        float4 v = *(const float4*)&g_Q[base + (size_t)(it * 64 + r) * HH + h4 * 4];
        v.x *= scale; v.y *= scale; v.z *= scale; v.w *= scale;
        *(float4*)&Qs[r][h4 * 4] = v;
    }

    float o[4][4];
    float m_r[4], l_r[4];
    #pragma unroll
    for (int i = 0; i < 4; i++) {
        m_r[i] = -1e30f; l_r[i] = 0.f;
        #pragma unroll
        for (int j = 0; j < 4; j++) o[i][j] = 0.f;
    }

    for (int jt = 0; jt <= it; jt++) {
        __syncthreads();   // protect smem reuse vs previous iteration readers
        // load K tile and V tile (V transposed into Vt[h][kv])
        #pragma unroll
        for (int t = 0; t < 4; t++) {
            int f = tid + t * 256;
            int r = f >> 4, h4 = f & 15;
            size_t g = base + (size_t)(jt * 64 + r) * HH + h4 * 4;
            float4 kv = *(const float4*)&g_K[g];
            *(float4*)&Ks[r][h4 * 4] = kv;
            float4 vv = *(const float4*)&g_V[g];
            Vt[h4 * 4 + 0][r] = vv.x;
            Vt[h4 * 4 + 1][r] = vv.y;
            Vt[h4 * 4 + 2][r] = vv.z;
            Vt[h4 * 4 + 3][r] = vv.w;
        }
        __syncthreads();

        // S = Q @ K^T  (4x4 per thread)
        float s[4][4];
        #pragma unroll
        for (int i = 0; i < 4; i++)
            #pragma unroll
            for (int j = 0; j < 4; j++) s[i][j] = 0.f;

        #pragma unroll
        for (int h = 0; h < 64; h += 4) {
            float4 q4[4], k4[4];
            #pragma unroll
            for (int i = 0; i < 4; i++) q4[i] = *(float4*)&Qs[ty + 16 * i][h];
            #pragma unroll
            for (int j = 0; j < 4; j++) k4[j] = *(float4*)&Ks[tx + 16 * j][h];
            #pragma unroll
            for (int i = 0; i < 4; i++)
                #pragma unroll
                for (int j = 0; j < 4; j++)
                    s[i][j] += q4[i].x * k4[j].x + q4[i].y * k4[j].y
                             + q4[i].z * k4[j].z + q4[i].w * k4[j].w;
        }

        // causal mask (only the diagonal tile is partial)
        if (jt == it) {
            #pragma unroll
            for (int i = 0; i < 4; i++)
                #pragma unroll
                for (int j = 0; j < 4; j++)
                    if (tx + 16 * j > ty + 16 * i) s[i][j] = -1e30f;
        }

        // online softmax update (row reductions across the 16 tx lanes)
        #pragma unroll
        for (int i = 0; i < 4; i++) {
            float mx = fmaxf(fmaxf(s[i][0], s[i][1]), fmaxf(s[i][2], s[i][3]));
            #pragma unroll
            for (int off = 1; off < 16; off <<= 1)
                mx = fmaxf(mx, __shfl_xor_sync(0xffffffffu, mx, off));
            float m_new = fmaxf(m_r[i], mx);
            float alpha = __expf(m_r[i] - m_new);
            float ls = 0.f;
            #pragma unroll
            for (int j = 0; j < 4; j++) {
                s[i][j] = __expf(s[i][j] - m_new);
                ls += s[i][j];
            }
            #pragma unroll
            for (int off = 1; off < 16; off <<= 1)
                ls += __shfl_xor_sync(0xffffffffu, ls, off);
            m_r[i] = m_new;
            l_r[i] = l_r[i] * alpha + ls;
            #pragma unroll
            for (int j = 0; j < 4; j++) o[i][j] *= alpha;
            #pragma unroll
            for (int j = 0; j < 4; j++) Ps[ty + 16 * i][tx + 16 * j] = s[i][j];
        }
        __syncthreads();

        // O += P @ V   (Vt is [h][kv], P is [q][kv] -> dot along kv)
        #pragma unroll
        for (int c = 0; c < 64; c += 4) {
            float4 p4[4], v4[4];
            #pragma unroll
            for (int i = 0; i < 4; i++) p4[i] = *(float4*)&Ps[ty + 16 * i][c];
            #pragma unroll
            for (int j = 0; j < 4; j++) v4[j] = *(float4*)&Vt[tx + 16 * j][c];
            #pragma unroll
            for (int i = 0; i < 4; i++)
                #pragma unroll
                for (int j = 0; j < 4; j++)
                    o[i][j] += p4[i].x * v4[j].x + p4[i].y * v4[j].y
                             + p4[i].z * v4[j].z + p4[i].w * v4[j].w;
        }
    }

    // epilogue: normalize and store (coalesced across tx)
    #pragma unroll
    for (int i = 0; i < 4; i++) {
        float inv = 1.f / l_r[i];
        int r = it * 64 + ty + 16 * i;
        #pragma unroll
        for (int j = 0; j < 4; j++)
            out[base + (size_t)r * HH + tx + 16 * j] = o[i][j] * inv;
    }
}

// ---------------------------------------------------------------------------
extern "C" void kernel_launch(void* const* d_in, const int* in_sizes, int n_in,
                              void* d_out, int out_size)
{
    const float* x  = (const float*)d_in[0];
    const float* Wq = (const float*)d_in[1];
    const float* Wk = (const float*)d_in[2];
    const float* Wv = (const float*)d_in[3];
    float* out = (float*)d_out;

    qkv_kernel<<<MM / 64, 256>>>(x, Wq, Wk, Wv);

    const int smem_bytes = 4 * 64 * 68 * (int)sizeof(float);   // 69632 B
    cudaFuncSetAttribute(attn_kernel,
                         cudaFuncAttributeMaxDynamicSharedMemorySize, smem_bytes);
    attn_kernel<<<dim3(TT / 64, BB), 256, smem_bytes>>>(out);
}

// round 2
// speedup vs baseline: 3.1058x; 3.1058x over previous
#include <cuda_runtime.h>
#include <cstddef>

#define BB 16
#define TT 2048
#define CC 1024
#define HH 64
#define MM (BB*TT)   // 32768 rows

// Scratch for projected Q,K,V (allocation-free rule: device globals)
__device__ float g_Q[(size_t)MM*HH];
__device__ float g_K[(size_t)MM*HH];
__device__ float g_V[(size_t)MM*HH];

// ---------------------------------------------------------------------------
// tf32 helpers
// ---------------------------------------------------------------------------
__device__ __forceinline__ unsigned f2tf(float f) {
    unsigned r;
    asm("cvt.rna.tf32.f32 %0, %1;" : "=r"(r) : "f"(f));
    return r;
}

__device__ __forceinline__ void mma_tf32(float* d, const unsigned* a,
                                         const unsigned* b, const float* c) {
    asm volatile(
        "mma.sync.aligned.m16n8k8.row.col.f32.tf32.tf32.f32 "
        "{%0,%1,%2,%3}, {%4,%5,%6,%7}, {%8,%9}, {%10,%11,%12,%13};"
        : "=f"(d[0]), "=f"(d[1]), "=f"(d[2]), "=f"(d[3])
        : "r"(a[0]), "r"(a[1]), "r"(a[2]), "r"(a[3]),
          "r"(b[0]), "r"(b[1]),
          "f"(c[0]), "f"(c[1]), "f"(c[2]), "f"(c[3]));
}

// ---------------------------------------------------------------------------
// Kernel 1: fused QKV projection, tf32 tensor cores.
// [32768,1024] @ [1024,64] x3.  CTA: 256 thr (8 warps), tile 128m x 192n, BK=32.
// Warp grid: 4 (m strips of 32) x 2 (n halves of 96).
// ---------------------------------------------------------------------------
__global__ __launch_bounds__(256) void qkv_kernel(
    const float* __restrict__ x,
    const float* __restrict__ Wq,
    const float* __restrict__ Wk,
    const float* __restrict__ Wv)
{
    __shared__ unsigned As[128][36];   // [m][k] tf32 bits (pad->conflict-free)
    __shared__ unsigned Bs[32][196];   // [k][n] tf32 bits, n = 3*64

    const int tid  = threadIdx.x;
    const int lane = tid & 31;
    const int wid  = tid >> 5;
    const int wm   = wid & 3;          // m strip (32 rows)
    const int wn   = wid >> 2;         // n half (96 cols)
    const int g    = lane >> 2;        // group id (0..7)
    const int t    = lane & 3;         // thread-in-group (0..3)
    const int m0   = blockIdx.x * 128;

    const float* Ws[3] = {Wq, Wk, Wv};

    float acc[2][12][4];
    #pragma unroll
    for (int mt = 0; mt < 2; mt++)
        #pragma unroll
        for (int nt = 0; nt < 12; nt++)
            #pragma unroll
            for (int e = 0; e < 4; e++) acc[mt][nt][e] = 0.f;

    for (int k0 = 0; k0 < CC; k0 += 32) {
        __syncthreads();
        // A tile: 128x32 -> 1024 float4, 4 per thread
        #pragma unroll
        for (int i = 0; i < 4; i++) {
            int f = tid + i * 256;
            int row = f >> 3, c4 = f & 7;
            float4 v = *(const float4*)&x[(size_t)(m0 + row) * CC + k0 + c4 * 4];
            uint4 u = {f2tf(v.x), f2tf(v.y), f2tf(v.z), f2tf(v.w)};
            *(uint4*)&As[row][c4 * 4] = u;
        }
        // B tiles: 3 x (32x64) -> 512 float4 each
        #pragma unroll
        for (int mat = 0; mat < 3; mat++) {
            #pragma unroll
            for (int j = 0; j < 2; j++) {
                int f = tid + j * 256;
                int r = f >> 4, c4 = f & 15;
                float4 v = *(const float4*)&Ws[mat][(size_t)(k0 + r) * HH + c4 * 4];
                uint4 u = {f2tf(v.x), f2tf(v.y), f2tf(v.z), f2tf(v.w)};
                *(uint4*)&Bs[r][mat * 64 + c4 * 4] = u;
            }
        }
        __syncthreads();

        #pragma unroll
        for (int kt = 0; kt < 4; kt++) {
            unsigned a[2][4];
            #pragma unroll
            for (int mt = 0; mt < 2; mt++) {
                int row = wm * 32 + mt * 16;
                a[mt][0] = As[row + g    ][kt * 8 + t    ];
                a[mt][1] = As[row + g + 8][kt * 8 + t    ];
                a[mt][2] = As[row + g    ][kt * 8 + t + 4];
                a[mt][3] = As[row + g + 8][kt * 8 + t + 4];
            }
            #pragma unroll
            for (int nt = 0; nt < 12; nt++) {
                int n = wn * 96 + nt * 8;
                unsigned b[2];
                b[0] = Bs[kt * 8 + t    ][n + g];
                b[1] = Bs[kt * 8 + t + 4][n + g];
                mma_tf32(acc[0][nt], a[0], b, acc[0][nt]);
                mma_tf32(acc[1][nt], a[1], b, acc[1][nt]);
            }
        }
    }

    // epilogue: scatter to g_Q/g_K/g_V
    #pragma unroll
    for (int mt = 0; mt < 2; mt++) {
        #pragma unroll
        for (int nt = 0; nt < 12; nt++) {
            int n   = wn * 96 + nt * 8 + 2 * t;
            int mat = n >> 6, col = n & 63;
            float* O = (mat == 0) ? g_Q : (mat == 1) ? g_K : g_V;
            int row = m0 + wm * 32 + mt * 16 + g;
            float2 v0 = {acc[mt][nt][0], acc[mt][nt][1]};
            float2 v1 = {acc[mt][nt][2], acc[mt][nt][3]};
            *(float2*)&O[(size_t)row * HH + col]       = v0;
            *(float2*)&O[(size_t)(row + 8) * HH + col] = v1;
        }
    }
}

// ---------------------------------------------------------------------------
// Kernel 2: causal flash attention, tf32 tensor cores.
// CTA: 128 thr (4 warps), BM=64 (warp = 16-row strip), BN=64 per kv step.
// ---------------------------------------------------------------------------
__global__ __launch_bounds__(128) void attn_kernel(float* __restrict__ out)
{
    extern __shared__ unsigned sm[];
    unsigned (*Qs)[68] = (unsigned(*)[68])(sm);              // [q][h]   tf32 (pre-scaled)
    unsigned (*Ks)[68] = (unsigned(*)[68])(sm + 64 * 68);    // [kv][h]  tf32
    unsigned (*Vs)[68] = (unsigned(*)[68])(sm + 2 * 64 * 68);// [kv][h]  tf32
    unsigned (*Ps)[68] = (unsigned(*)[68])(sm + 3 * 64 * 68);// [q][kv]  tf32

    const int tid  = threadIdx.x;
    const int lane = tid & 31;
    const int wid  = tid >> 5;        // 0..3, owns q rows [16w, 16w+16)
    const int g    = lane >> 2;
    const int t    = lane & 3;
    const int b    = blockIdx.y;
    const int it   = gridDim.x - 1 - blockIdx.x;   // heavy tiles first

    const size_t base  = (size_t)b * TT * HH;
    const float  qscale = 0.03125f * 1.44269504f;  // C^-0.5 * log2(e)

    // load Q tile (scaled, tf32)
    #pragma unroll
    for (int i = 0; i < 8; i++) {
        int f = tid + i * 128;
        int r = f >> 4, c4 = f & 15;
        float4 v = *(const float4*)&g_Q[base + (size_t)(it * 64 + r) * HH + c4 * 4];
        uint4 u = {f2tf(v.x * qscale), f2tf(v.y * qscale),
                   f2tf(v.z * qscale), f2tf(v.w * qscale)};
        *(uint4*)&Qs[r][c4 * 4] = u;
    }

    float o[8][4];
    #pragma unroll
    for (int nt = 0; nt < 8; nt++)
        #pragma unroll
        for (int e = 0; e < 4; e++) o[nt][e] = 0.f;
    float m0r = -1e30f, m1r = -1e30f, l0r = 0.f, l1r = 0.f;

    const int qrow = wid * 16 + g;     // thread's first q row (local)

    for (int jt = 0; jt <= it; jt++) {
        __syncthreads();
        // load K,V tiles (tf32)
        #pragma unroll
        for (int i = 0; i < 8; i++) {
            int f = tid + i * 128;
            int r = f >> 4, c4 = f & 15;
            size_t gaddr = base + (size_t)(jt * 64 + r) * HH + c4 * 4;
            float4 kv = *(const float4*)&g_K[gaddr];
            uint4 uk = {f2tf(kv.x), f2tf(kv.y), f2tf(kv.z), f2tf(kv.w)};
            *(uint4*)&Ks[r][c4 * 4] = uk;
            float4 vv = *(const float4*)&g_V[gaddr];
            uint4 uv = {f2tf(vv.x), f2tf(vv.y), f2tf(vv.z), f2tf(vv.w)};
            *(uint4*)&Vs[r][c4 * 4] = uv;
        }
        __syncthreads();

        // preload Q fragments for all 8 k-tiles (reused across 8 n-tiles)
        unsigned aq[8][4];
        #pragma unroll
        for (int kt = 0; kt < 8; kt++) {
            aq[kt][0] = Qs[qrow    ][kt * 8 + t    ];
            aq[kt][1] = Qs[qrow + 8][kt * 8 + t    ];
            aq[kt][2] = Qs[qrow    ][kt * 8 + t + 4];
            aq[kt][3] = Qs[qrow + 8][kt * 8 + t + 4];
        }

        // S = Q @ K^T
        float s[8][4];
        #pragma unroll
        for (int nt = 0; nt < 8; nt++) {
            float sa[4] = {0.f, 0.f, 0.f, 0.f};
            #pragma unroll
            for (int kt = 0; kt < 8; kt++) {
                unsigned bk[2];
                bk[0] = Ks[nt * 8 + g][kt * 8 + t    ];
                bk[1] = Ks[nt * 8 + g][kt * 8 + t + 4];
                mma_tf32(sa, aq[kt], bk, sa);
            }
            s[nt][0] = sa[0]; s[nt][1] = sa[1]; s[nt][2] = sa[2]; s[nt][3] = sa[3];
        }

        // causal mask (diagonal tile only)
        if (jt == it) {
            #pragma unroll
            for (int nt = 0; nt < 8; nt++) {
                int c = nt * 8 + 2 * t;
                if (c     > qrow    ) s[nt][0] = -1e30f;
                if (c + 1 > qrow    ) s[nt][1] = -1e30f;
                if (c     > qrow + 8) s[nt][2] = -1e30f;
                if (c + 1 > qrow + 8) s[nt][3] = -1e30f;
            }
        }

        // online softmax (rows qrow and qrow+8; quad = lanes sharing g)
        float mx0 = -1e30f, mx1 = -1e30f;
        #pragma unroll
        for (int nt = 0; nt < 8; nt++) {
            mx0 = fmaxf(mx0, fmaxf(s[nt][0], s[nt][1]));
            mx1 = fmaxf(mx1, fmaxf(s[nt][2], s[nt][3]));
        }
        mx0 = fmaxf(mx0, __shfl_xor_sync(0xffffffffu, mx0, 1));
        mx0 = fmaxf(mx0, __shfl_xor_sync(0xffffffffu, mx0, 2));
        mx1 = fmaxf(mx1, __shfl_xor_sync(0xffffffffu, mx1, 1));
        mx1 = fmaxf(mx1, __shfl_xor_sync(0xffffffffu, mx1, 2));

        float mn0 = fmaxf(m0r, mx0), mn1 = fmaxf(m1r, mx1);
        float al0 = exp2f(m0r - mn0), al1 = exp2f(m1r - mn1);
        float sum0 = 0.f, sum1 = 0.f;
        #pragma unroll
        for (int nt = 0; nt < 8; nt++) {
            s[nt][0] = exp2f(s[nt][0] - mn0);
            s[nt][1] = exp2f(s[nt][1] - mn0);
            s[nt][2] = exp2f(s[nt][2] - mn1);
            s[nt][3] = exp2f(s[nt][3] - mn1);
            sum0 += s[nt][0] + s[nt][1];
            sum1 += s[nt][2] + s[nt][3];
        }
        sum0 += __shfl_xor_sync(0xffffffffu, sum0, 1);
        sum0 += __shfl_xor_sync(0xffffffffu, sum0, 2);
        sum1 += __shfl_xor_sync(0xffffffffu, sum1, 1);
        sum1 += __shfl_xor_sync(0xffffffffu, sum1, 2);
        m0r = mn0; m1r = mn1;
        l0r = l0r * al0 + sum0;
        l1r = l1r * al1 + sum1;
        #pragma unroll
        for (int nt = 0; nt < 8; nt++) {
            o[nt][0] *= al0; o[nt][1] *= al0;
            o[nt][2] *= al1; o[nt][3] *= al1;
        }

        // store P (warp-private rows -> only syncwarp needed)
        #pragma unroll
        for (int nt = 0; nt < 8; nt++) {
            uint2 u0 = {f2tf(s[nt][0]), f2tf(s[nt][1])};
            uint2 u1 = {f2tf(s[nt][2]), f2tf(s[nt][3])};
            *(uint2*)&Ps[qrow    ][nt * 8 + 2 * t] = u0;
            *(uint2*)&Ps[qrow + 8][nt * 8 + 2 * t] = u1;
        }
        __syncwarp();

        // O += P @ V
        #pragma unroll
        for (int kt = 0; kt < 8; kt++) {
            unsigned ap[4];
            ap[0] = Ps[qrow    ][kt * 8 + t    ];
            ap[1] = Ps[qrow + 8][kt * 8 + t    ];
            ap[2] = Ps[qrow    ][kt * 8 + t + 4];
            ap[3] = Ps[qrow + 8][kt * 8 + t + 4];
            #pragma unroll
            for (int nt = 0; nt < 8; nt++) {
                unsigned bv[2];
                bv[0] = Vs[kt * 8 + t    ][nt * 8 + g];
                bv[1] = Vs[kt * 8 + t + 4][nt * 8 + g];
                mma_tf32(o[nt], ap, bv, o[nt]);
            }
        }
    }

    // epilogue
    float inv0 = 1.f / l0r, inv1 = 1.f / l1r;
    int r0 = it * 64 + qrow;
    #pragma unroll
    for (int nt = 0; nt < 8; nt++) {
        int c = nt * 8 + 2 * t;
        float2 v0 = {o[nt][0] * inv0, o[nt][1] * inv0};
        float2 v1 = {o[nt][2] * inv1, o[nt][3] * inv1};
        *(float2*)&out[base + (size_t)r0 * HH + c]       = v0;
        *(float2*)&out[base + (size_t)(r0 + 8) * HH + c] = v1;
    }
}

// ---------------------------------------------------------------------------
extern "C" void kernel_launch(void* const* d_in, const int* in_sizes, int n_in,
                              void* d_out, int out_size)
{
    const float* x  = (const float*)d_in[0];
    const float* Wq = (const float*)d_in[1];
    const float* Wk = (const float*)d_in[2];
    const float* Wv = (const float*)d_in[3];
    float* out = (float*)d_out;

    qkv_kernel<<<MM / 128, 256>>>(x, Wq, Wk, Wv);

    const int smem_bytes = 4 * 64 * 68 * (int)sizeof(unsigned);  // 69632 B
    cudaFuncSetAttribute(attn_kernel,
                         cudaFuncAttributeMaxDynamicSharedMemorySize, smem_bytes);
    attn_kernel<<<dim3(TT / 64, BB), 128, smem_bytes>>>(out);
}

// round 4
// speedup vs baseline: 6.3329x; 2.0390x over previous
#include <cuda_runtime.h>
#include <cuda_fp16.h>
#include <cstddef>
#include <cstdint>

#define BB 16
#define TT 2048
#define CC 1024
#define HH 64
#define MM (BB*TT)   // 32768 rows

// fp16 scratch for projected Q,K,V (Q pre-scaled by C^-0.5 * log2(e))
__device__ __half g_Q[(size_t)MM*HH];
__device__ __half g_K[(size_t)MM*HH];
__device__ __half g_V[(size_t)MM*HH];

// ---------------------------------------------------------------------------
// helpers
// ---------------------------------------------------------------------------
__device__ __forceinline__ uint32_t smem_u32(const void* p) {
    return (uint32_t)__cvta_generic_to_shared(p);
}

__device__ __forceinline__ void ldsm4(uint32_t addr, unsigned& r0, unsigned& r1,
                                      unsigned& r2, unsigned& r3) {
    asm volatile("ldmatrix.sync.aligned.m8n8.x4.shared.b16 {%0,%1,%2,%3}, [%4];"
                 : "=r"(r0), "=r"(r1), "=r"(r2), "=r"(r3) : "r"(addr));
}

__device__ __forceinline__ void ldsm4t(uint32_t addr, unsigned& r0, unsigned& r1,
                                       unsigned& r2, unsigned& r3) {
    asm volatile("ldmatrix.sync.aligned.m8n8.x4.trans.shared.b16 {%0,%1,%2,%3}, [%4];"
                 : "=r"(r0), "=r"(r1), "=r"(r2), "=r"(r3) : "r"(addr));
}

__device__ __forceinline__ void mma16816(float* d, const unsigned* a,
                                         unsigned b0, unsigned b1, const float* c) {
    asm volatile(
        "mma.sync.aligned.m16n8k16.row.col.f32.f16.f16.f32 "
        "{%0,%1,%2,%3}, {%4,%5,%6,%7}, {%8,%9}, {%10,%11,%12,%13};"
        : "=f"(d[0]), "=f"(d[1]), "=f"(d[2]), "=f"(d[3])
        : "r"(a[0]), "r"(a[1]), "r"(a[2]), "r"(a[3]),
          "r"(b0), "r"(b1),
          "f"(c[0]), "f"(c[1]), "f"(c[2]), "f"(c[3]));
}

__device__ __forceinline__ float ex2(float x) {
    float y;
    asm("ex2.approx.ftz.f32 %0, %1;" : "=f"(y) : "f"(x));
    return y;
}

// ---------------------------------------------------------------------------
// Kernel 1: fused QKV projection, fp16 MMA + ldmatrix.
// [32768,1024] @ [1024,64] x3. CTA: 256 thr (8 warps: 4m x 2n),
// tile 128m x 192n, BK=32. Outputs fp16 (Q pre-scaled).
// ---------------------------------------------------------------------------
__global__ __launch_bounds__(256) void qkv_kernel(
    const float* __restrict__ x,
    const float* __restrict__ Wq,
    const float* __restrict__ Wk,
    const float* __restrict__ Wv)
{
    __shared__ __half As[128][40];   // [m][k]  (pad 8 -> ldmatrix conflict-free)
    __shared__ __half Bs[32][200];   // [k][n]  n = 3*64 + pad 8

    const int tid  = threadIdx.x;
    const int lane = tid & 31;
    const int wid  = tid >> 5;
    const int wm   = wid & 3;        // m strip of 32
    const int wn   = wid >> 2;       // n half of 96
    const int sub  = lane >> 3;      // ldmatrix sub-matrix id
    const int rr   = lane & 7;       // ldmatrix row-in-matrix
    const int g    = lane >> 2;
    const int t    = lane & 3;
    const int m0   = blockIdx.x * 128;

    const float* Ws[3] = {Wq, Wk, Wv};

    float acc[2][12][4];
    #pragma unroll
    for (int mt = 0; mt < 2; mt++)
        #pragma unroll
        for (int nt = 0; nt < 12; nt++)
            #pragma unroll
            for (int e = 0; e < 4; e++) acc[mt][nt][e] = 0.f;

    for (int k0 = 0; k0 < CC; k0 += 32) {
        __syncthreads();
        // A: 128x32 fp32 -> fp16 smem
        #pragma unroll
        for (int i = 0; i < 4; i++) {
            int idx = tid + i * 256;
            int row = idx >> 3, c4 = idx & 7;
            float4 v = *(const float4*)&x[(size_t)(m0 + row) * CC + k0 + c4 * 4];
            __half2 h01 = __floats2half2_rn(v.x, v.y);
            __half2 h23 = __floats2half2_rn(v.z, v.w);
            __half2* p = (__half2*)&As[row][c4 * 4];
            p[0] = h01; p[1] = h23;
        }
        // B: 3 x (32k x 64n) fp32 -> fp16 smem [k][n]
        #pragma unroll
        for (int mat = 0; mat < 3; mat++) {
            #pragma unroll
            for (int j = 0; j < 2; j++) {
                int idx = tid + j * 256;
                int r = idx >> 4, c4 = idx & 15;
                float4 v = *(const float4*)&Ws[mat][(size_t)(k0 + r) * HH + c4 * 4];
                __half2 h01 = __floats2half2_rn(v.x, v.y);
                __half2 h23 = __floats2half2_rn(v.z, v.w);
                __half2* p = (__half2*)&Bs[r][mat * 64 + c4 * 4];
                p[0] = h01; p[1] = h23;
            }
        }
        __syncthreads();

        #pragma unroll
        for (int kt = 0; kt < 2; kt++) {
            unsigned a[2][4];
            #pragma unroll
            for (int mt = 0; mt < 2; mt++) {
                int row0 = wm * 32 + mt * 16;
                uint32_t ad = smem_u32(&As[row0 + (sub & 1) * 8 + rr]
                                          [kt * 16 + (sub >> 1) * 8]);
                ldsm4(ad, a[mt][0], a[mt][1], a[mt][2], a[mt][3]);
            }
            #pragma unroll
            for (int p = 0; p < 6; p++) {
                int n0 = wn * 96 + p * 16;
                unsigned b0, b1, b2, b3;
                uint32_t bd = smem_u32(&Bs[kt * 16 + (sub & 1) * 8 + rr]
                                          [n0 + (sub >> 1) * 8]);
                ldsm4t(bd, b0, b1, b2, b3);
                #pragma unroll
                for (int mt = 0; mt < 2; mt++) {
                    mma16816(acc[mt][2 * p    ], a[mt], b0, b1, acc[mt][2 * p    ]);
                    mma16816(acc[mt][2 * p + 1], a[mt], b2, b3, acc[mt][2 * p + 1]);
                }
            }
        }
    }

    // epilogue: fp16 stores (Q pre-scaled by C^-0.5 * log2 e)
    const float QS = 0.03125f * 1.44269504f;
    #pragma unroll
    for (int mt = 0; mt < 2; mt++) {
        #pragma unroll
        for (int nt = 0; nt < 12; nt++) {
            int n = wn * 96 + nt * 8 + 2 * t;
            int mat = n >> 6, col = n & 63;          // never straddles (2t<8)
            __half* O = (mat == 0) ? g_Q : (mat == 1) ? g_K : g_V;
            float sc = (mat == 0) ? QS : 1.f;
            int row = m0 + wm * 32 + mt * 16 + g;
            __half2 h0 = __floats2half2_rn(acc[mt][nt][0] * sc, acc[mt][nt][1] * sc);
            __half2 h1 = __floats2half2_rn(acc[mt][nt][2] * sc, acc[mt][nt][3] * sc);
            *(__half2*)&O[(size_t)row * HH + col]       = h0;
            *(__half2*)&O[(size_t)(row + 8) * HH + col] = h1;
        }
    }
}

// ---------------------------------------------------------------------------
// Kernel 2: causal flash attention, fp16 MMA + ldmatrix.
// CTA: 128 thr (4 warps), BM=64 per pass, BN=64.
// Each CTA processes q-tile pair (x, 31-x) -> uniform 33 kv-steps/CTA.
// ---------------------------------------------------------------------------
__global__ __launch_bounds__(128) void attn_kernel(float* __restrict__ out)
{
    __shared__ __half Qs[64][72];
    __shared__ __half Ks[64][72];
    __shared__ __half Vs[64][72];
    __shared__ __half Ps[64][72];

    const int tid  = threadIdx.x;
    const int lane = tid & 31;
    const int wid  = tid >> 5;        // q rows [16w, 16w+16)
    const int sub  = lane >> 3;
    const int rr   = lane & 7;
    const int g    = lane >> 2;
    const int t    = lane & 3;
    const int b    = blockIdx.y;

    const size_t base = (size_t)b * TT * HH;
    const int row0 = wid * 16;
    const int qrow = row0 + g;

    #pragma unroll
    for (int pass = 0; pass < 2; pass++) {
        const int it = (pass == 0) ? blockIdx.x : (2 * gridDim.x - 1 - blockIdx.x);

        __syncthreads();
        // load Q tile (fp16, pre-scaled)
        #pragma unroll
        for (int i = 0; i < 4; i++) {
            int idx = tid + i * 128;
            int r = idx >> 3, c = idx & 7;
            *(uint4*)&Qs[r][c * 8] =
                *(const uint4*)&g_Q[base + (size_t)(it * 64 + r) * HH + c * 8];
        }
        __syncthreads();

        // preload Q A-fragments (constant across kv loop)
        unsigned aq[4][4];
        #pragma unroll
        for (int kt = 0; kt < 4; kt++) {
            uint32_t ad = smem_u32(&Qs[row0 + (sub & 1) * 8 + rr]
                                      [kt * 16 + (sub >> 1) * 8]);
            ldsm4(ad, aq[kt][0], aq[kt][1], aq[kt][2], aq[kt][3]);
        }

        float o[8][4];
        #pragma unroll
        for (int nt = 0; nt < 8; nt++)
            #pragma unroll
            for (int e = 0; e < 4; e++) o[nt][e] = 0.f;
        float m0r = -1e30f, m1r = -1e30f, l0r = 0.f, l1r = 0.f;

        for (int jt = 0; jt <= it; jt++) {
            __syncthreads();
            // load K,V tiles
            #pragma unroll
            for (int i = 0; i < 4; i++) {
                int idx = tid + i * 128;
                int r = idx >> 3, c = idx & 7;
                size_t ga = base + (size_t)(jt * 64 + r) * HH + c * 8;
                *(uint4*)&Ks[r][c * 8] = *(const uint4*)&g_K[ga];
                *(uint4*)&Vs[r][c * 8] = *(const uint4*)&g_V[ga];
            }
            __syncthreads();

            // S = Q @ K^T  (log2-scaled already)
            float s[8][4];
            #pragma unroll
            for (int nt = 0; nt < 8; nt++)
                #pragma unroll
                for (int e = 0; e < 4; e++) s[nt][e] = 0.f;

            #pragma unroll
            for (int kt = 0; kt < 4; kt++) {
                #pragma unroll
                for (int p = 0; p < 4; p++) {
                    unsigned b0, b1, b2, b3;
                    uint32_t kd = smem_u32(&Ks[p * 16 + (sub >> 1) * 8 + rr]
                                              [kt * 16 + (sub & 1) * 8]);
                    ldsm4(kd, b0, b1, b2, b3);
                    mma16816(s[2 * p    ], aq[kt], b0, b1, s[2 * p    ]);
                    mma16816(s[2 * p + 1], aq[kt], b2, b3, s[2 * p + 1]);
                }
            }

            // causal mask (diagonal tile only)
            if (jt == it) {
                #pragma unroll
                for (int nt = 0; nt < 8; nt++) {
                    int c = nt * 8 + 2 * t;
                    if (c     > qrow    ) s[nt][0] = -1e30f;
                    if (c + 1 > qrow    ) s[nt][1] = -1e30f;
                    if (c     > qrow + 8) s[nt][2] = -1e30f;
                    if (c + 1 > qrow + 8) s[nt][3] = -1e30f;
                }
            }

            // online softmax (base-2)
            float mx0 = -1e30f, mx1 = -1e30f;
            #pragma unroll
            for (int nt = 0; nt < 8; nt++) {
                mx0 = fmaxf(mx0, fmaxf(s[nt][0], s[nt][1]));
                mx1 = fmaxf(mx1, fmaxf(s[nt][2], s[nt][3]));
            }
            mx0 = fmaxf(mx0, __shfl_xor_sync(0xffffffffu, mx0, 1));
            mx0 = fmaxf(mx0, __shfl_xor_sync(0xffffffffu, mx0, 2));
            mx1 = fmaxf(mx1, __shfl_xor_sync(0xffffffffu, mx1, 1));
            mx1 = fmaxf(mx1, __shfl_xor_sync(0xffffffffu, mx1, 2));

            float mn0 = fmaxf(m0r, mx0), mn1 = fmaxf(m1r, mx1);
            float al0 = ex2(m0r - mn0), al1 = ex2(m1r - mn1);
            float sum0 = 0.f, sum1 = 0.f;
            #pragma unroll
            for (int nt = 0; nt < 8; nt++) {
                s[nt][0] = ex2(s[nt][0] - mn0);
                s[nt][1] = ex2(s[nt][1] - mn0);
                s[nt][2] = ex2(s[nt][2] - mn1);
                s[nt][3] = ex2(s[nt][3] - mn1);
                sum0 += s[nt][0] + s[nt][1];
                sum1 += s[nt][2] + s[nt][3];
            }
            sum0 += __shfl_xor_sync(0xffffffffu, sum0, 1);
            sum0 += __shfl_xor_sync(0xffffffffu, sum0, 2);
            sum1 += __shfl_xor_sync(0xffffffffu, sum1, 1);
            sum1 += __shfl_xor_sync(0xffffffffu, sum1, 2);
            m0r = mn0; m1r = mn1;
            l0r = l0r * al0 + sum0;
            l1r = l1r * al1 + sum1;
            #pragma unroll
            for (int nt = 0; nt < 8; nt++) {
                o[nt][0] *= al0; o[nt][1] *= al0;
                o[nt][2] *= al1; o[nt][3] *= al1;
            }

            // P -> smem (warp-private rows), fp16
            #pragma unroll
            for (int nt = 0; nt < 8; nt++) {
                *(__half2*)&Ps[qrow    ][nt * 8 + 2 * t] =
                    __floats2half2_rn(s[nt][0], s[nt][1]);
                *(__half2*)&Ps[qrow + 8][nt * 8 + 2 * t] =
                    __floats2half2_rn(s[nt][2], s[nt][3]);
            }
            __syncwarp();

            // O += P @ V
            #pragma unroll
            for (int kt = 0; kt < 4; kt++) {
                unsigned pa[4];
                uint32_t pd = smem_u32(&Ps[row0 + (sub & 1) * 8 + rr]
                                          [kt * 16 + (sub >> 1) * 8]);
                ldsm4(pd, pa[0], pa[1], pa[2], pa[3]);
                #pragma unroll
                for (int p = 0; p < 4; p++) {
                    unsigned v0, v1, v2, v3;
                    uint32_t vd = smem_u32(&Vs[kt * 16 + (sub & 1) * 8 + rr]
                                              [p * 16 + (sub >> 1) * 8]);
                    ldsm4t(vd, v0, v1, v2, v3);
                    mma16816(o[2 * p    ], pa, v0, v1, o[2 * p    ]);
                    mma16816(o[2 * p + 1], pa, v2, v3, o[2 * p + 1]);
                }
            }
        }

        // epilogue
        float inv0 = 1.f / l0r, inv1 = 1.f / l1r;
        int r0 = it * 64 + qrow;
        #pragma unroll
        for (int nt = 0; nt < 8; nt++) {
            int c = nt * 8 + 2 * t;
            float2 v0 = {o[nt][0] * inv0, o[nt][1] * inv0};
            float2 v1 = {o[nt][2] * inv1, o[nt][3] * inv1};
            *(float2*)&out[base + (size_t)r0 * HH + c]       = v0;
            *(float2*)&out[base + (size_t)(r0 + 8) * HH + c] = v1;
        }
    }
}

// ---------------------------------------------------------------------------
extern "C" void kernel_launch(void* const* d_in, const int* in_sizes, int n_in,
                              void* d_out, int out_size)
{
    const float* x  = (const float*)d_in[0];
    const float* Wq = (const float*)d_in[1];
    const float* Wk = (const float*)d_in[2];
    const float* Wv = (const float*)d_in[3];
    float* out = (float*)d_out;

    qkv_kernel<<<MM / 128, 256>>>(x, Wq, Wk, Wv);
    attn_kernel<<<dim3(16, BB), 128>>>(out);
}

// round 8
// speedup vs baseline: 7.3319x; 1.1577x over previous
#include <cuda_runtime.h>
#include <cuda_fp16.h>
#include <cstddef>
#include <cstdint>

#define BB 16
#define TT 2048
#define CC 1024
#define HH 64
#define MM (BB*TT)   // 32768 rows

// fp16 scratch for projected Q,K,V (Q pre-scaled by C^-0.5 * log2(e))
__device__ __half g_Q[(size_t)MM*HH];
__device__ __half g_K[(size_t)MM*HH];
__device__ __half g_V[(size_t)MM*HH];

// ---------------------------------------------------------------------------
// helpers
// ---------------------------------------------------------------------------
__device__ __forceinline__ uint32_t smem_u32(const void* p) {
    return (uint32_t)__cvta_generic_to_shared(p);
}

__device__ __forceinline__ void ldsm4(uint32_t addr, unsigned& r0, unsigned& r1,
                                      unsigned& r2, unsigned& r3) {
    asm volatile("ldmatrix.sync.aligned.m8n8.x4.shared.b16 {%0,%1,%2,%3}, [%4];"
                 : "=r"(r0), "=r"(r1), "=r"(r2), "=r"(r3) : "r"(addr));
}

__device__ __forceinline__ void ldsm4t(uint32_t addr, unsigned& r0, unsigned& r1,
                                       unsigned& r2, unsigned& r3) {
    asm volatile("ldmatrix.sync.aligned.m8n8.x4.trans.shared.b16 {%0,%1,%2,%3}, [%4];"
                 : "=r"(r0), "=r"(r1), "=r"(r2), "=r"(r3) : "r"(addr));
}

__device__ __forceinline__ void mma16816(float* d, const unsigned* a,
                                         unsigned b0, unsigned b1, const float* c) {
    asm volatile(
        "mma.sync.aligned.m16n8k16.row.col.f32.f16.f16.f32 "
        "{%0,%1,%2,%3}, {%4,%5,%6,%7}, {%8,%9}, {%10,%11,%12,%13};"
        : "=f"(d[0]), "=f"(d[1]), "=f"(d[2]), "=f"(d[3])
        : "r"(a[0]), "r"(a[1]), "r"(a[2]), "r"(a[3]),
          "r"(b0), "r"(b1),
          "f"(c[0]), "f"(c[1]), "f"(c[2]), "f"(c[3]));
}

__device__ __forceinline__ float ex2(float x) {
    float y;
    asm("ex2.approx.ftz.f32 %0, %1;" : "=f"(y) : "f"(x));
    return y;
}

__device__ __forceinline__ void cp16(uint32_t dst, const void* src) {
    asm volatile("cp.async.cg.shared.global [%0], [%1], 16;" :: "r"(dst), "l"(src));
}
#define CP_COMMIT() asm volatile("cp.async.commit_group;")
#define CP_WAIT(N)  asm volatile("cp.async.wait_group %0;" :: "n"(N))

__device__ __forceinline__ unsigned h2u(__half2 h) {
    return *reinterpret_cast<unsigned*>(&h);
}

// ---------------------------------------------------------------------------
// Kernel 1: fused QKV projection, fp16 MMA + ldmatrix + register double-buffer.
// [32768,1024] @ [1024,64] x3. CTA: 256 thr (8 warps: 4m x 2n),
// tile 64m x 192n, BK=32. Outputs fp16 (Q pre-scaled).
// ---------------------------------------------------------------------------
__global__ __launch_bounds__(256, 2) void qkv_kernel(
    const float* __restrict__ x,
    const float* __restrict__ Wq,
    const float* __restrict__ Wk,
    const float* __restrict__ Wv)
{
    __shared__ __half As[64][40];    // [m][k]
    __shared__ __half Bs[32][200];   // [k][n]  n = 3*64 + pad 8

    const int tid  = threadIdx.x;
    const int lane = tid & 31;
    const int wid  = tid >> 5;
    const int wm   = wid & 3;        // m strip of 16
    const int wn   = wid >> 2;       // n half of 96
    const int sub  = lane >> 3;
    const int rr   = lane & 7;
    const int g    = lane >> 2;
    const int t    = lane & 3;
    const int m0   = blockIdx.x * 64;

    const float* Ws[3] = {Wq, Wk, Wv};

    // register staging
    float4 ax[2], bw[6];
    const int a_row = (tid >> 3),          a_c4 = (tid & 7);           // +i*32 rows
    const int b_row = (tid >> 4),          b_c4 = (tid & 15);          // +j*16 rows

    float acc[12][4];
    #pragma unroll
    for (int nt = 0; nt < 12; nt++)
        #pragma unroll
        for (int e = 0; e < 4; e++) acc[nt][e] = 0.f;

    // prologue: load k0=0 tile into regs
    #pragma unroll
    for (int i = 0; i < 2; i++)
        ax[i] = *(const float4*)&x[(size_t)(m0 + a_row + i * 32) * CC + a_c4 * 4];
    #pragma unroll
    for (int mat = 0; mat < 3; mat++)
        #pragma unroll
        for (int j = 0; j < 2; j++)
            bw[mat * 2 + j] = *(const float4*)&Ws[mat][(size_t)(b_row + j * 16) * HH + b_c4 * 4];

    for (int k0 = 0; k0 < CC; k0 += 32) {
        // store staged regs -> smem
        #pragma unroll
        for (int i = 0; i < 2; i++) {
            __half2* p = (__half2*)&As[a_row + i * 32][a_c4 * 4];
            p[0] = __floats2half2_rn(ax[i].x, ax[i].y);
            p[1] = __floats2half2_rn(ax[i].z, ax[i].w);
        }
        #pragma unroll
        for (int mat = 0; mat < 3; mat++)
            #pragma unroll
            for (int j = 0; j < 2; j++) {
                float4 v = bw[mat * 2 + j];
                __half2* p = (__half2*)&Bs[b_row + j * 16][mat * 64 + b_c4 * 4];
                p[0] = __floats2half2_rn(v.x, v.y);
                p[1] = __floats2half2_rn(v.z, v.w);
            }
        __syncthreads();

        // issue next tile's global loads (overlap with MMA below)
        if (k0 + 32 < CC) {
            #pragma unroll
            for (int i = 0; i < 2; i++)
                ax[i] = *(const float4*)&x[(size_t)(m0 + a_row + i * 32) * CC
                                           + k0 + 32 + a_c4 * 4];
            #pragma unroll
            for (int mat = 0; mat < 3; mat++)
                #pragma unroll
                for (int j = 0; j < 2; j++)
                    bw[mat * 2 + j] = *(const float4*)
                        &Ws[mat][(size_t)(k0 + 32 + b_row + j * 16) * HH + b_c4 * 4];
        }

        // compute
        #pragma unroll
        for (int kt = 0; kt < 2; kt++) {
            unsigned a[4];
            uint32_t ad = smem_u32(&As[wm * 16 + (sub & 1) * 8 + rr]
                                      [kt * 16 + (sub >> 1) * 8]);
            ldsm4(ad, a[0], a[1], a[2], a[3]);
            #pragma unroll
            for (int p = 0; p < 6; p++) {
                unsigned b0, b1, b2, b3;
                uint32_t bd = smem_u32(&Bs[kt * 16 + (sub & 1) * 8 + rr]
                                          [wn * 96 + p * 16 + (sub >> 1) * 8]);
                ldsm4t(bd, b0, b1, b2, b3);
                mma16816(acc[2 * p    ], a, b0, b1, acc[2 * p    ]);
                mma16816(acc[2 * p + 1], a, b2, b3, acc[2 * p + 1]);
            }
        }
        __syncthreads();
    }

    // epilogue: fp16 stores (Q pre-scaled)
    const float QS = 0.03125f * 1.44269504f;
    #pragma unroll
    for (int nt = 0; nt < 12; nt++) {
        int n = wn * 96 + nt * 8 + 2 * t;
        int mat = n >> 6, col = n & 63;
        __half* O = (mat == 0) ? g_Q : (mat == 1) ? g_K : g_V;
        float sc = (mat == 0) ? QS : 1.f;
        int row = m0 + wm * 16 + g;
        *(__half2*)&O[(size_t)row * HH + col] =
            __floats2half2_rn(acc[nt][0] * sc, acc[nt][1] * sc);
        *(__half2*)&O[(size_t)(row + 8) * HH + col] =
            __floats2half2_rn(acc[nt][2] * sc, acc[nt][3] * sc);
    }
}

// ---------------------------------------------------------------------------
// Kernel 2: causal flash attention, fp16 MMA, register-resident P,
// cp.async double-buffered K/V.  CTA: 128 thr (4 warps), BM=64, BN=64.
// Each CTA processes q-tile pair (x, 31-x) -> uniform 33 kv-steps.
// ---------------------------------------------------------------------------
__global__ __launch_bounds__(128) void attn_kernel(float* __restrict__ out)
{
    __shared__ __half Qs[64][72];
    __shared__ __half Ks[2][64][72];
    __shared__ __half Vs[2][64][72];

    const int tid  = threadIdx.x;
    const int lane = tid & 31;
    const int wid  = tid >> 5;        // q rows [16w, 16w+16)
    const int sub  = lane >> 3;
    const int rr   = lane & 7;
    const int g    = lane >> 2;
    const int t    = lane & 3;
    const int b    = blockIdx.y;

    const size_t base = (size_t)b * TT * HH;
    const int row0 = wid * 16;
    const int qrow = row0 + g;

    const int kv_r  = tid >> 3;       // row for cp.async (64 rows, 8 chunks each)
    const int kv_c  = tid & 7;

    #pragma unroll
    for (int pass = 0; pass < 2; pass++) {
        const int it = (pass == 0) ? (int)blockIdx.x : (31 - (int)blockIdx.x);

        __syncthreads();   // smem free from previous pass

        // stage 0 K/V via cp.async
        {
            const size_t ga = base + (size_t)kv_r * HH + kv_c * 8;
            #pragma unroll
            for (int i = 0; i < 4; i++) {
                cp16(smem_u32(&Ks[0][kv_r + i * 16][kv_c * 8]),
                     &g_K[ga + (size_t)i * 16 * HH]);
                cp16(smem_u32(&Vs[0][kv_r + i * 16][kv_c * 8]),
                     &g_V[ga + (size_t)i * 16 * HH]);
            }
        }
        CP_COMMIT();

        // load Q tile
        #pragma unroll
        for (int i = 0; i < 4; i++) {
            int idx = tid + i * 128;
            int r = idx >> 3, c = idx & 7;
            *(uint4*)&Qs[r][c * 8] =
                *(const uint4*)&g_Q[base + (size_t)(it * 64 + r) * HH + c * 8];
        }
        __syncthreads();

        unsigned aq[4][4];
        #pragma unroll
        for (int kt = 0; kt < 4; kt++) {
            uint32_t ad = smem_u32(&Qs[row0 + (sub & 1) * 8 + rr]
                                      [kt * 16 + (sub >> 1) * 8]);
            ldsm4(ad, aq[kt][0], aq[kt][1], aq[kt][2], aq[kt][3]);
        }

        float o[8][4];
        #pragma unroll
        for (int nt = 0; nt < 8; nt++)
            #pragma unroll
            for (int e = 0; e < 4; e++) o[nt][e] = 0.f;
        float m0r = -1e30f, m1r = -1e30f, l0r = 0.f, l1r = 0.f;

        for (int jt = 0; jt <= it; jt++) {
            const int cur = jt & 1;

            if (jt < it) {   // prefetch next stage
                const size_t ga = base + (size_t)((jt + 1) * 64 + kv_r) * HH + kv_c * 8;
                #pragma unroll
                for (int i = 0; i < 4; i++) {
                    cp16(smem_u32(&Ks[cur ^ 1][kv_r + i * 16][kv_c * 8]),
                         &g_K[ga + (size_t)i * 16 * HH]);
                    cp16(smem_u32(&Vs[cur ^ 1][kv_r + i * 16][kv_c * 8]),
                         &g_V[ga + (size_t)i * 16 * HH]);
                }
                CP_COMMIT();
                CP_WAIT(1);
            } else {
                CP_WAIT(0);
            }
            __syncthreads();

            // S = Q @ K^T
            float s[8][4];
            #pragma unroll
            for (int nt = 0; nt < 8; nt++)
                #pragma unroll
                for (int e = 0; e < 4; e++) s[nt][e] = 0.f;

            #pragma unroll
            for (int kt = 0; kt < 4; kt++) {
                #pragma unroll
                for (int p = 0; p < 4; p++) {
                    unsigned b0, b1, b2, b3;
                    uint32_t kd = smem_u32(&Ks[cur][p * 16 + (sub >> 1) * 8 + rr]
                                              [kt * 16 + (sub & 1) * 8]);
                    ldsm4(kd, b0, b1, b2, b3);
                    mma16816(s[2 * p    ], aq[kt], b0, b1, s[2 * p    ]);
                    mma16816(s[2 * p + 1], aq[kt], b2, b3, s[2 * p + 1]);
                }
            }

            // causal mask (diagonal tile only)
            if (jt == it) {
                #pragma unroll
                for (int nt = 0; nt < 8; nt++) {
                    int c = nt * 8 + 2 * t;
                    if (c     > qrow    ) s[nt][0] = -1e30f;
                    if (c + 1 > qrow    ) s[nt][1] = -1e30f;
                    if (c     > qrow + 8) s[nt][2] = -1e30f;
                    if (c + 1 > qrow + 8) s[nt][3] = -1e30f;
                }
            }

            // online softmax (base-2; Q pre-scaled by log2 e)
            float mx0 = -1e30f, mx1 = -1e30f;
            #pragma unroll
            for (int nt = 0; nt < 8; nt++) {
                mx0 = fmaxf(mx0, fmaxf(s[nt][0], s[nt][1]));
                mx1 = fmaxf(mx1, fmaxf(s[nt][2], s[nt][3]));
            }
            mx0 = fmaxf(mx0, __shfl_xor_sync(0xffffffffu, mx0, 1));
            mx0 = fmaxf(mx0, __shfl_xor_sync(0xffffffffu, mx0, 2));
            mx1 = fmaxf(mx1, __shfl_xor_sync(0xffffffffu, mx1, 1));
            mx1 = fmaxf(mx1, __shfl_xor_sync(0xffffffffu, mx1, 2));

            float mn0 = fmaxf(m0r, mx0), mn1 = fmaxf(m1r, mx1);
            float al0 = ex2(m0r - mn0), al1 = ex2(m1r - mn1);
            float sum0 = 0.f, sum1 = 0.f;
            __half2 ph0[8], ph1[8];
            #pragma unroll
            for (int nt = 0; nt < 8; nt++) {
                s[nt][0] = ex2(s[nt][0] - mn0);
                s[nt][1] = ex2(s[nt][1] - mn0);
                s[nt][2] = ex2(s[nt][2] - mn1);
                s[nt][3] = ex2(s[nt][3] - mn1);
                sum0 += s[nt][0] + s[nt][1];
                sum1 += s[nt][2] + s[nt][3];
                ph0[nt] = __floats2half2_rn(s[nt][0], s[nt][1]);
                ph1[nt] = __floats2half2_rn(s[nt][2], s[nt][3]);
            }
            sum0 += __shfl_xor_sync(0xffffffffu, sum0, 1);
            sum0 += __shfl_xor_sync(0xffffffffu, sum0, 2);
            sum1 += __shfl_xor_sync(0xffffffffu, sum1, 1);
            sum1 += __shfl_xor_sync(0xffffffffu, sum1, 2);
            m0r = mn0; m1r = mn1;
            l0r = l0r * al0 + sum0;
            l1r = l1r * al1 + sum1;
            #pragma unroll
            for (int nt = 0; nt < 8; nt++) {
                o[nt][0] *= al0; o[nt][1] *= al0;
                o[nt][2] *= al1; o[nt][3] *= al1;
            }

            // O += P @ V   (P stays in registers: C-frag layout == A-frag layout)
            #pragma unroll
            for (int kt = 0; kt < 4; kt++) {
                unsigned pa[4] = { h2u(ph0[2 * kt]),     h2u(ph1[2 * kt]),
                                   h2u(ph0[2 * kt + 1]), h2u(ph1[2 * kt + 1]) };
                #pragma unroll
                for (int p = 0; p < 4; p++) {
                    unsigned v0, v1, v2, v3;
                    uint32_t vd = smem_u32(&Vs[cur][kt * 16 + (sub & 1) * 8 + rr]
                                              [p * 16 + (sub >> 1) * 8]);
                    ldsm4t(vd, v0, v1, v2, v3);
                    mma16816(o[2 * p    ], pa, v0, v1, o[2 * p    ]);
                    mma16816(o[2 * p + 1], pa, v2, v3, o[2 * p + 1]);
                }
            }
            __syncthreads();   // all warps done with buf[cur] before it is refilled
        }

        // epilogue
        float inv0 = 1.f / l0r, inv1 = 1.f / l1r;
        int r0 = it * 64 + qrow;
        #pragma unroll
        for (int nt = 0; nt < 8; nt++) {
            int c = nt * 8 + 2 * t;
            float2 v0 = {o[nt][0] * inv0, o[nt][1] * inv0};
            float2 v1 = {o[nt][2] * inv1, o[nt][3] * inv1};
            *(float2*)&out[base + (size_t)r0 * HH + c]       = v0;
            *(float2*)&out[base + (size_t)(r0 + 8) * HH + c] = v1;
        }
    }
}

// ---------------------------------------------------------------------------
extern "C" void kernel_launch(void* const* d_in, const int* in_sizes, int n_in,
                              void* d_out, int out_size)
{
    const float* x  = (const float*)d_in[0];
    const float* Wq = (const float*)d_in[1];
    const float* Wk = (const float*)d_in[2];
    const float* Wv = (const float*)d_in[3];
    float* out = (float*)d_out;

    qkv_kernel<<<MM / 64, 256>>>(x, Wq, Wk, Wv);
    attn_kernel<<<dim3(16, BB), 128>>>(out);
}

// round 9
// speedup vs baseline: 7.3339x; 1.0003x over previous
#include <cuda_runtime.h>
#include <cuda_fp16.h>
#include <cstddef>
#include <cstdint>

#define BB 16
#define TT 2048
#define CC 1024
#define HH 64
#define MM (BB*TT)   // 32768 rows

// fp16 scratch for projected Q,K,V (Q pre-scaled by C^-0.5 * log2(e))
__device__ __half g_Q[(size_t)MM*HH];
__device__ __half g_K[(size_t)MM*HH];
__device__ __half g_V[(size_t)MM*HH];

// ---------------------------------------------------------------------------
// helpers
// ---------------------------------------------------------------------------
__device__ __forceinline__ uint32_t smem_u32(const void* p) {
    return (uint32_t)__cvta_generic_to_shared(p);
}

__device__ __forceinline__ void ldsm4(uint32_t addr, unsigned& r0, unsigned& r1,
                                      unsigned& r2, unsigned& r3) {
    asm volatile("ldmatrix.sync.aligned.m8n8.x4.shared.b16 {%0,%1,%2,%3}, [%4];"
                 : "=r"(r0), "=r"(r1), "=r"(r2), "=r"(r3) : "r"(addr));
}

__device__ __forceinline__ void ldsm4t(uint32_t addr, unsigned& r0, unsigned& r1,
                                       unsigned& r2, unsigned& r3) {
    asm volatile("ldmatrix.sync.aligned.m8n8.x4.trans.shared.b16 {%0,%1,%2,%3}, [%4];"
                 : "=r"(r0), "=r"(r1), "=r"(r2), "=r"(r3) : "r"(addr));
}

__device__ __forceinline__ void mma16816(float* d, const unsigned* a,
                                         unsigned b0, unsigned b1, const float* c) {
    asm volatile(
        "mma.sync.aligned.m16n8k16.row.col.f32.f16.f16.f32 "
        "{%0,%1,%2,%3}, {%4,%5,%6,%7}, {%8,%9}, {%10,%11,%12,%13};"
        : "=f"(d[0]), "=f"(d[1]), "=f"(d[2]), "=f"(d[3])
        : "r"(a[0]), "r"(a[1]), "r"(a[2]), "r"(a[3]),
          "r"(b0), "r"(b1),
          "f"(c[0]), "f"(c[1]), "f"(c[2]), "f"(c[3]));
}

__device__ __forceinline__ float ex2(float x) {
    float y;
    asm("ex2.approx.ftz.f32 %0, %1;" : "=f"(y) : "f"(x));
    return y;
}

__device__ __forceinline__ void cp16(uint32_t dst, const void* src) {
    asm volatile("cp.async.cg.shared.global [%0], [%1], 16;" :: "r"(dst), "l"(src));
}
#define CP_COMMIT() asm volatile("cp.async.commit_group;")
#define CP_WAIT(N)  asm volatile("cp.async.wait_group %0;" :: "n"(N))

__device__ __forceinline__ unsigned h2u(__half2 h) {
    return *reinterpret_cast<unsigned*>(&h);
}

// ---------------------------------------------------------------------------
// Kernel 1: fused QKV projection, fp16 MMA + ldmatrix + register double-buffer.
// [32768,1024] @ [1024,64] x3. CTA: 256 thr (8 warps: 4m x 2n),
// tile 64m x 192n, BK=32. Outputs fp16 (Q pre-scaled).
// ---------------------------------------------------------------------------
__global__ __launch_bounds__(256, 2) void qkv_kernel(
    const float* __restrict__ x,
    const float* __restrict__ Wq,
    const float* __restrict__ Wk,
    const float* __restrict__ Wv)
{
    __shared__ __half As[64][40];    // [m][k]
    __shared__ __half Bs[32][200];   // [k][n]  n = 3*64 + pad 8

    const int tid  = threadIdx.x;
    const int lane = tid & 31;
    const int wid  = tid >> 5;
    const int wm   = wid & 3;        // m strip of 16
    const int wn   = wid >> 2;       // n half of 96
    const int sub  = lane >> 3;
    const int rr   = lane & 7;
    const int g    = lane >> 2;
    const int t    = lane & 3;
    const int m0   = blockIdx.x * 64;

    const float* Ws[3] = {Wq, Wk, Wv};

    // register staging
    float4 ax[2], bw[6];
    const int a_row = (tid >> 3),          a_c4 = (tid & 7);           // +i*32 rows
    const int b_row = (tid >> 4),          b_c4 = (tid & 15);          // +j*16 rows

    float acc[12][4];
    #pragma unroll
    for (int nt = 0; nt < 12; nt++)
        #pragma unroll
        for (int e = 0; e < 4; e++) acc[nt][e] = 0.f;

    // prologue: load k0=0 tile into regs
    #pragma unroll
    for (int i = 0; i < 2; i++)
        ax[i] = *(const float4*)&x[(size_t)(m0 + a_row + i * 32) * CC + a_c4 * 4];
    #pragma unroll
    for (int mat = 0; mat < 3; mat++)
        #pragma unroll
        for (int j = 0; j < 2; j++)
            bw[mat * 2 + j] = *(const float4*)&Ws[mat][(size_t)(b_row + j * 16) * HH + b_c4 * 4];

    for (int k0 = 0; k0 < CC; k0 += 32) {
        // store staged regs -> smem
        #pragma unroll
        for (int i = 0; i < 2; i++) {
            __half2* p = (__half2*)&As[a_row + i * 32][a_c4 * 4];
            p[0] = __floats2half2_rn(ax[i].x, ax[i].y);
            p[1] = __floats2half2_rn(ax[i].z, ax[i].w);
        }
        #pragma unroll
        for (int mat = 0; mat < 3; mat++)
            #pragma unroll
            for (int j = 0; j < 2; j++) {
                float4 v = bw[mat * 2 + j];
                __half2* p = (__half2*)&Bs[b_row + j * 16][mat * 64 + b_c4 * 4];
                p[0] = __floats2half2_rn(v.x, v.y);
                p[1] = __floats2half2_rn(v.z, v.w);
            }
        __syncthreads();

        // issue next tile's global loads (overlap with MMA below)
        if (k0 + 32 < CC) {
            #pragma unroll
            for (int i = 0; i < 2; i++)
                ax[i] = *(const float4*)&x[(size_t)(m0 + a_row + i * 32) * CC
                                           + k0 + 32 + a_c4 * 4];
            #pragma unroll
            for (int mat = 0; mat < 3; mat++)
                #pragma unroll
                for (int j = 0; j < 2; j++)
                    bw[mat * 2 + j] = *(const float4*)
                        &Ws[mat][(size_t)(k0 + 32 + b_row + j * 16) * HH + b_c4 * 4];
        }

        // compute
        #pragma unroll
        for (int kt = 0; kt < 2; kt++) {
            unsigned a[4];
            uint32_t ad = smem_u32(&As[wm * 16 + (sub & 1) * 8 + rr]
                                      [kt * 16 + (sub >> 1) * 8]);
            ldsm4(ad, a[0], a[1], a[2], a[3]);
            #pragma unroll
            for (int p = 0; p < 6; p++) {
                unsigned b0, b1, b2, b3;
                uint32_t bd = smem_u32(&Bs[kt * 16 + (sub & 1) * 8 + rr]
                                          [wn * 96 + p * 16 + (sub >> 1) * 8]);
                ldsm4t(bd, b0, b1, b2, b3);
                mma16816(acc[2 * p    ], a, b0, b1, acc[2 * p    ]);
                mma16816(acc[2 * p + 1], a, b2, b3, acc[2 * p + 1]);
            }
        }
        __syncthreads();
    }

    // epilogue: fp16 stores (Q pre-scaled)
    const float QS = 0.03125f * 1.44269504f;
    #pragma unroll
    for (int nt = 0; nt < 12; nt++) {
        int n = wn * 96 + nt * 8 + 2 * t;
        int mat = n >> 6, col = n & 63;
        __half* O = (mat == 0) ? g_Q : (mat == 1) ? g_K : g_V;
        float sc = (mat == 0) ? QS : 1.f;
        int row = m0 + wm * 16 + g;
        *(__half2*)&O[(size_t)row * HH + col] =
            __floats2half2_rn(acc[nt][0] * sc, acc[nt][1] * sc);
        *(__half2*)&O[(size_t)(row + 8) * HH + col] =
            __floats2half2_rn(acc[nt][2] * sc, acc[nt][3] * sc);
    }
}

// ---------------------------------------------------------------------------
// Kernel 2: causal flash attention, fp16 MMA, register-resident P,
// cp.async double-buffered K/V.  CTA: 128 thr (4 warps), BM=64, BN=64.
// Each CTA processes q-tile pair (x, 31-x) -> uniform 33 kv-steps.
// ---------------------------------------------------------------------------
__global__ __launch_bounds__(128) void attn_kernel(float* __restrict__ out)
{
    __shared__ __half Qs[64][72];
    __shared__ __half Ks[2][64][72];
    __shared__ __half Vs[2][64][72];

    const int tid  = threadIdx.x;
    const int lane = tid & 31;
    const int wid  = tid >> 5;        // q rows [16w, 16w+16)
    const int sub  = lane >> 3;
    const int rr   = lane & 7;
    const int g    = lane >> 2;
    const int t    = lane & 3;
    const int b    = blockIdx.y;

    const size_t base = (size_t)b * TT * HH;
    const int row0 = wid * 16;
    const int qrow = row0 + g;

    const int kv_r  = tid >> 3;       // row for cp.async (64 rows, 8 chunks each)
    const int kv_c  = tid & 7;

    #pragma unroll
    for (int pass = 0; pass < 2; pass++) {
        const int it = (pass == 0) ? (int)blockIdx.x : (31 - (int)blockIdx.x);

        __syncthreads();   // smem free from previous pass

        // stage 0 K/V via cp.async
        {
            const size_t ga = base + (size_t)kv_r * HH + kv_c * 8;
            #pragma unroll
            for (int i = 0; i < 4; i++) {
                cp16(smem_u32(&Ks[0][kv_r + i * 16][kv_c * 8]),
                     &g_K[ga + (size_t)i * 16 * HH]);
                cp16(smem_u32(&Vs[0][kv_r + i * 16][kv_c * 8]),
                     &g_V[ga + (size_t)i * 16 * HH]);
            }
        }
        CP_COMMIT();

        // load Q tile
        #pragma unroll
        for (int i = 0; i < 4; i++) {
            int idx = tid + i * 128;
            int r = idx >> 3, c = idx & 7;
            *(uint4*)&Qs[r][c * 8] =
                *(const uint4*)&g_Q[base + (size_t)(it * 64 + r) * HH + c * 8];
        }
        __syncthreads();

        unsigned aq[4][4];
        #pragma unroll
        for (int kt = 0; kt < 4; kt++) {
            uint32_t ad = smem_u32(&Qs[row0 + (sub & 1) * 8 + rr]
                                      [kt * 16 + (sub >> 1) * 8]);
            ldsm4(ad, aq[kt][0], aq[kt][1], aq[kt][2], aq[kt][3]);
        }

        float o[8][4];
        #pragma unroll
        for (int nt = 0; nt < 8; nt++)
            #pragma unroll
            for (int e = 0; e < 4; e++) o[nt][e] = 0.f;
        float m0r = -1e30f, m1r = -1e30f, l0r = 0.f, l1r = 0.f;

        for (int jt = 0; jt <= it; jt++) {
            const int cur = jt & 1;

            if (jt < it) {   // prefetch next stage
                const size_t ga = base + (size_t)((jt + 1) * 64 + kv_r) * HH + kv_c * 8;
                #pragma unroll
                for (int i = 0; i < 4; i++) {
                    cp16(smem_u32(&Ks[cur ^ 1][kv_r + i * 16][kv_c * 8]),
                         &g_K[ga + (size_t)i * 16 * HH]);
                    cp16(smem_u32(&Vs[cur ^ 1][kv_r + i * 16][kv_c * 8]),
                         &g_V[ga + (size_t)i * 16 * HH]);
                }
                CP_COMMIT();
                CP_WAIT(1);
            } else {
                CP_WAIT(0);
            }
            __syncthreads();

            // S = Q @ K^T
            float s[8][4];
            #pragma unroll
            for (int nt = 0; nt < 8; nt++)
                #pragma unroll
                for (int e = 0; e < 4; e++) s[nt][e] = 0.f;

            #pragma unroll
            for (int kt = 0; kt < 4; kt++) {
                #pragma unroll
                for (int p = 0; p < 4; p++) {
                    unsigned b0, b1, b2, b3;
                    uint32_t kd = smem_u32(&Ks[cur][p * 16 + (sub >> 1) * 8 + rr]
                                              [kt * 16 + (sub & 1) * 8]);
                    ldsm4(kd, b0, b1, b2, b3);
                    mma16816(s[2 * p    ], aq[kt], b0, b1, s[2 * p    ]);
                    mma16816(s[2 * p + 1], aq[kt], b2, b3, s[2 * p + 1]);
                }
            }

            // causal mask (diagonal tile only)
            if (jt == it) {
                #pragma unroll
                for (int nt = 0; nt < 8; nt++) {
                    int c = nt * 8 + 2 * t;
                    if (c     > qrow    ) s[nt][0] = -1e30f;
                    if (c + 1 > qrow    ) s[nt][1] = -1e30f;
                    if (c     > qrow + 8) s[nt][2] = -1e30f;
                    if (c + 1 > qrow + 8) s[nt][3] = -1e30f;
                }
            }

            // online softmax (base-2; Q pre-scaled by log2 e)
            float mx0 = -1e30f, mx1 = -1e30f;
            #pragma unroll
            for (int nt = 0; nt < 8; nt++) {
                mx0 = fmaxf(mx0, fmaxf(s[nt][0], s[nt][1]));
                mx1 = fmaxf(mx1, fmaxf(s[nt][2], s[nt][3]));
            }
            mx0 = fmaxf(mx0, __shfl_xor_sync(0xffffffffu, mx0, 1));
            mx0 = fmaxf(mx0, __shfl_xor_sync(0xffffffffu, mx0, 2));
            mx1 = fmaxf(mx1, __shfl_xor_sync(0xffffffffu, mx1, 1));
            mx1 = fmaxf(mx1, __shfl_xor_sync(0xffffffffu, mx1, 2));

            float mn0 = fmaxf(m0r, mx0), mn1 = fmaxf(m1r, mx1);
            float al0 = ex2(m0r - mn0), al1 = ex2(m1r - mn1);
            float sum0 = 0.f, sum1 = 0.f;
            __half2 ph0[8], ph1[8];
            #pragma unroll
            for (int nt = 0; nt < 8; nt++) {
                s[nt][0] = ex2(s[nt][0] - mn0);
                s[nt][1] = ex2(s[nt][1] - mn0);
                s[nt][2] = ex2(s[nt][2] - mn1);
                s[nt][3] = ex2(s[nt][3] - mn1);
                sum0 += s[nt][0] + s[nt][1];
                sum1 += s[nt][2] + s[nt][3];
                ph0[nt] = __floats2half2_rn(s[nt][0], s[nt][1]);
                ph1[nt] = __floats2half2_rn(s[nt][2], s[nt][3]);
            }
            sum0 += __shfl_xor_sync(0xffffffffu, sum0, 1);
            sum0 += __shfl_xor_sync(0xffffffffu, sum0, 2);
            sum1 += __shfl_xor_sync(0xffffffffu, sum1, 1);
            sum1 += __shfl_xor_sync(0xffffffffu, sum1, 2);
            m0r = mn0; m1r = mn1;
            l0r = l0r * al0 + sum0;
            l1r = l1r * al1 + sum1;
            #pragma unroll
            for (int nt = 0; nt < 8; nt++) {
                o[nt][0] *= al0; o[nt][1] *= al0;
                o[nt][2] *= al1; o[nt][3] *= al1;
            }

            // O += P @ V   (P stays in registers: C-frag layout == A-frag layout)
            #pragma unroll
            for (int kt = 0; kt < 4; kt++) {
                unsigned pa[4] = { h2u(ph0[2 * kt]),     h2u(ph1[2 * kt]),
                                   h2u(ph0[2 * kt + 1]), h2u(ph1[2 * kt + 1]) };
                #pragma unroll
                for (int p = 0; p < 4; p++) {
                    unsigned v0, v1, v2, v3;
                    uint32_t vd = smem_u32(&Vs[cur][kt * 16 + (sub & 1) * 8 + rr]
                                              [p * 16 + (sub >> 1) * 8]);
                    ldsm4t(vd, v0, v1, v2, v3);
                    mma16816(o[2 * p    ], pa, v0, v1, o[2 * p    ]);
                    mma16816(o[2 * p + 1], pa, v2, v3, o[2 * p + 1]);
                }
            }
            __syncthreads();   // all warps done with buf[cur] before it is refilled
        }

        // epilogue
        float inv0 = 1.f / l0r, inv1 = 1.f / l1r;
        int r0 = it * 64 + qrow;
        #pragma unroll
        for (int nt = 0; nt < 8; nt++) {
            int c = nt * 8 + 2 * t;
            float2 v0 = {o[nt][0] * inv0, o[nt][1] * inv0};
            float2 v1 = {o[nt][2] * inv1, o[nt][3] * inv1};
            *(float2*)&out[base + (size_t)r0 * HH + c]       = v0;
            *(float2*)&out[base + (size_t)(r0 + 8) * HH + c] = v1;
        }
    }
}

// ---------------------------------------------------------------------------
extern "C" void kernel_launch(void* const* d_in, const int* in_sizes, int n_in,
                              void* d_out, int out_size)
{
    const float* x  = (const float*)d_in[0];
    const float* Wq = (const float*)d_in[1];
    const float* Wk = (const float*)d_in[2];
    const float* Wv = (const float*)d_in[3];
    float* out = (float*)d_out;

    qkv_kernel<<<MM / 64, 256>>>(x, Wq, Wk, Wv);
    attn_kernel<<<dim3(16, BB), 128>>>(out);
}